// round 14
// baseline (speedup 1.0000x reference)
#include <cuda_runtime.h>

#define D        256
#define H        16
#define RTILE    256    // rows per block (= threads)
#define THREADS  256
#define CHUNK    16     // k-columns staged per chunk
#define NCH      16     // 256/16
#define XCFL     (RTILE * CHUNK)   // floats per stage buffer (4096)

typedef unsigned long long u64;

static __device__ __forceinline__ u64 pack2(float a, float b) {
    u64 r; asm("mov.b64 %0, {%1, %2};" : "=l"(r) : "f"(a), "f"(b)); return r;
}
static __device__ __forceinline__ void unpack2(u64 v, float& a, float& b) {
    asm("mov.b64 {%0, %1}, %2;" : "=f"(a), "=f"(b) : "l"(v));
}
static __device__ __forceinline__ u64 fma2(u64 a, u64 b, u64 c) {
    u64 d; asm("fma.rn.f32x2 %0, %1, %2, %3;" : "=l"(d) : "l"(a), "l"(b), "l"(c)); return d;
}
static __device__ __forceinline__ float ex2f(float x) {
    float r; asm("ex2.approx.f32 %0, %1;" : "=f"(r) : "f"(x)); return r;
}
static __device__ __forceinline__ float rcpf(float x) {
    float r; asm("rcp.approx.f32 %0, %1;" : "=f"(r) : "f"(x)); return r;
}
static __device__ __forceinline__ float sigmoid2(float s) {
    return rcpf(1.0f + ex2f(s * -2.8853900817779268f));
}
static __device__ __forceinline__ u64 mk_evict_last_policy() {
    u64 p; asm("createpolicy.fractional.L2::evict_last.b64 %0, 1.0;" : "=l"(p));
    return p;
}
static __device__ __forceinline__ void cpa16_el(float* dst, const float* src, u64 pol) {
    unsigned s = (unsigned)__cvta_generic_to_shared(dst);
    asm volatile("cp.async.ca.shared.global.L2::cache_hint [%0], [%1], 16, %2;"
                 :: "r"(s), "l"(src), "l"(pol) : "memory");
}
static __device__ __forceinline__ void cpa_commit() {
    asm volatile("cp.async.commit_group;" ::: "memory");
}

// Shared (floats): W1s [0,4096) | xcA [4096,8192) | xcB [8192,12288)
// hb (pass 2) reuses xcA: [256][16] quad-XOR swizzle. Total 48 KB -> 4 CTAs/SM.
__global__ __launch_bounds__(THREADS, 4)
void fb_kernel(const float* __restrict__ x, const float* __restrict__ W1,
               const float* __restrict__ W2, float* __restrict__ out, int n)
{
    extern __shared__ float smem[];
    float* W1s = smem;
    float* xcA = smem + 4096;
    float* xcB = smem + 8192;
    float* hb  = xcA;                      // union: valid after pass 1

    const int t     = threadIdx.x;
    const int row0  = blockIdx.x * RTILE;
    const int nrows = min(RTILE, n - row0);
    const u64 pol   = mk_evict_last_policy();

    // stage W1 (covered by first chunk's barrier)
    #pragma unroll
    for (int i = 0; i < 16; i++) W1s[t + i * THREADS] = W1[t + i * THREADS];

    // prologue: prefetch chunks 0 (A) and 1 (B), pinned evict_last in L2
    #pragma unroll
    for (int c = 0; c < 2; c++) {
        float* buf = c ? xcB : xcA;
        #pragma unroll
        for (int it = 0; it < 4; it++) {
            int idx = t + it * THREADS;    // 0..1023 float4 slots
            int rr = idx >> 2, q = idx & 3;
            if (rr < nrows)
                cpa16_el(buf + rr * CHUNK + 4 * (q ^ ((rr >> 1) & 3)),
                         x + (long long)(row0 + rr) * D + c * CHUNK + 4 * q, pol);
        }
        cpa_commit();
    }

    // ================= pass 1: h = relu(x @ W1), 1 row/thread ===============
    const int r   = t;
    const int qs1 = (r >> 1) & 3;
    u64 acc[8];
    #pragma unroll
    for (int i = 0; i < 8; i++) acc[i] = 0ULL;

    for (int c = 0; c < NCH; c++) {
        if (c < NCH - 1) asm volatile("cp.async.wait_group 1;" ::: "memory");
        else             asm volatile("cp.async.wait_group 0;" ::: "memory");
        __syncthreads();

        const float* myrow = (c & 1 ? xcB : xcA) + r * CHUNK;
        const float* wbase = W1s + c * CHUNK * H;
        #pragma unroll
        for (int q = 0; q < 4; q++) {
            float4 xv = *reinterpret_cast<const float4*>(myrow + 4 * (q ^ qs1));
            #pragma unroll
            for (int i = 0; i < 4; i++) {
                float xs = (i == 0) ? xv.x : (i == 1) ? xv.y : (i == 2) ? xv.z : xv.w;
                u64 xx = pack2(xs, xs);
                const ulonglong2* wq =
                    reinterpret_cast<const ulonglong2*>(wbase + (4 * q + i) * H);
                ulonglong2 wa = wq[0], wb = wq[1];
                acc[0] = fma2(xx, wa.x, acc[0]);
                acc[1] = fma2(xx, wa.y, acc[1]);
                acc[2] = fma2(xx, wb.x, acc[2]);
                acc[3] = fma2(xx, wb.y, acc[3]);
                ulonglong2 wc = wq[2], wd = wq[3];
                acc[4] = fma2(xx, wc.x, acc[4]);
                acc[5] = fma2(xx, wc.y, acc[5]);
                acc[6] = fma2(xx, wd.x, acc[6]);
                acc[7] = fma2(xx, wd.y, acc[7]);
            }
        }
        __syncthreads();                    // everyone done reading buf(c&1)

        if (c + 2 < NCH) {                  // prefetch c+2 into the freed buffer
            float* buf = (c & 1) ? xcB : xcA;
            #pragma unroll
            for (int it = 0; it < 4; it++) {
                int idx = t + it * THREADS;
                int rr = idx >> 2, q = idx & 3;
                if (rr < nrows)
                    cpa16_el(buf + rr * CHUNK + 4 * (q ^ ((rr >> 1) & 3)),
                             x + (long long)(row0 + rr) * D + (c + 2) * CHUNK + 4 * q, pol);
            }
            cpa_commit();
        }
    }

    // ReLU + store h row into hb (=xcA), quad-XOR swizzle -> conflict-free
    #pragma unroll
    for (int q = 0; q < 4; q++) {
        float a0, a1, b0, b1;
        unpack2(acc[2 * q + 0], a0, a1);
        unpack2(acc[2 * q + 1], b0, b1);
        float4 v = make_float4(fmaxf(a0, 0.f), fmaxf(a1, 0.f),
                               fmaxf(b0, 0.f), fmaxf(b1, 0.f));
        *reinterpret_cast<float4*>(hb + r * H + 4 * (q ^ qs1)) = v;
    }
    __syncthreads();

    // ========= pass 2: 1 k-column per warp, all 256 rows, 8-deep prefetch ====
    const int w = t >> 5, lane = t & 31;
    const int k = w * 32 + lane;           // 8 warps x 32 lanes = 256 columns

    u64 w2[8];                             // W2 column k, j-pairs
    #pragma unroll
    for (int j = 0; j < 8; j++)
        w2[j] = pack2(W2[(2 * j) * D + k], W2[(2 * j + 1) * D + k]);

    const float* xk = x   + (long long)row0 * D + k;
    float*       ok = out + (long long)row0 * D + k;

    float xp[8];                           // prefetch ring
    #pragma unroll
    for (int i = 0; i < 8; i++)
        xp[i] = (i < nrows) ? __ldcs(xk + i * D) : 0.f;

    #pragma unroll 8
    for (int rr = 0; rr < nrows; rr++) {
        float xv = xp[rr & 7];
        int pf = rr + 8;
        if (pf < nrows) xp[rr & 7] = __ldcs(xk + pf * D);

        int fq = (rr >> 1) & 3;            // uniform per warp -> broadcast LDS
        const float* hr = hb + rr * H;
        u64 sa = 0ULL, sb = 0ULL;
        {
            ulonglong2 h0 = *reinterpret_cast<const ulonglong2*>(hr + 4 * (0 ^ fq));
            ulonglong2 h1 = *reinterpret_cast<const ulonglong2*>(hr + 4 * (1 ^ fq));
            sa = fma2(h0.x, w2[0], sa);
            sb = fma2(h0.y, w2[1], sb);
            sa = fma2(h1.x, w2[2], sa);
            sb = fma2(h1.y, w2[3], sb);
            ulonglong2 h2 = *reinterpret_cast<const ulonglong2*>(hr + 4 * (2 ^ fq));
            ulonglong2 h3 = *reinterpret_cast<const ulonglong2*>(hr + 4 * (3 ^ fq));
            sa = fma2(h2.x, w2[4], sa);
            sb = fma2(h2.y, w2[5], sb);
            sa = fma2(h3.x, w2[6], sa);
            sb = fma2(h3.y, w2[7], sb);
        }
        float a0, a1;
        u64 s2 = fma2(pack2(1.f, 1.f), sa, sb);   // sa + sb packed
        unpack2(s2, a0, a1);
        float s = a0 + a1;

        __stcs(ok + (long long)rr * D, xv * sigmoid2(s));
    }
}

extern "C" void kernel_launch(void* const* d_in, const int* in_sizes, int n_in,
                              void* d_out, int out_size) {
    const float* x  = (const float*)d_in[0];
    const float* W1 = (const float*)d_in[1];
    const float* W2 = (const float*)d_in[2];
    float* out = (float*)d_out;
    int n = in_sizes[0] / D;

    int smem_bytes = (4096 + 2 * XCFL) * (int)sizeof(float);   // 48 KB -> 4 CTAs/SM
    cudaFuncSetAttribute(fb_kernel, cudaFuncAttributeMaxDynamicSharedMemorySize, smem_bytes);
    int grid = (n + RTILE - 1) / RTILE;
    fb_kernel<<<grid, THREADS, smem_bytes>>>(x, W1, W2, out, n);
}

// round 16
// speedup vs baseline: 1.2648x; 1.2648x over previous
#include <cuda_runtime.h>

#define D        256
#define H        16
#define RT1      256    // rows per block, kernel 1
#define TH1      256
#define CHUNK    16
#define NCH      16
#define XCFL     (RT1 * CHUNK)

#define RT2      128    // rows per block, kernel 2
#define TH2      256

typedef unsigned long long u64;

__device__ float h_scratch[8000000];   // 500000 * 16 floats = 32 MB

static __device__ __forceinline__ u64 pack2(float a, float b) {
    u64 r; asm("mov.b64 %0, {%1, %2};" : "=l"(r) : "f"(a), "f"(b)); return r;
}
static __device__ __forceinline__ void unpack2(u64 v, float& a, float& b) {
    asm("mov.b64 {%0, %1}, %2;" : "=f"(a), "=f"(b) : "l"(v));
}
static __device__ __forceinline__ u64 fma2(u64 a, u64 b, u64 c) {
    u64 d; asm("fma.rn.f32x2 %0, %1, %2, %3;" : "=l"(d) : "l"(a), "l"(b), "l"(c)); return d;
}
static __device__ __forceinline__ float ex2f(float x) {
    float r; asm("ex2.approx.f32 %0, %1;" : "=f"(r) : "f"(x)); return r;
}
static __device__ __forceinline__ float rcpf(float x) {
    float r; asm("rcp.approx.f32 %0, %1;" : "=f"(r) : "f"(x)); return r;
}
static __device__ __forceinline__ float sigmoid2(float s) {
    return rcpf(1.0f + ex2f(s * -2.8853900817779268f));
}
static __device__ __forceinline__ void cpa16(float* dst, const float* src) {
    unsigned s = (unsigned)__cvta_generic_to_shared(dst);
    asm volatile("cp.async.ca.shared.global [%0], [%1], 16;" :: "r"(s), "l"(src) : "memory");
}
static __device__ __forceinline__ void cpa_commit() {
    asm volatile("cp.async.commit_group;" ::: "memory");
}

// ============ Kernel 1: h = relu(x @ W1) -> h_scratch =======================
// Shared (floats): W1s [0,4096) | xcA [4096,8192) | xcB [8192,12288). 48 KB.
__global__ __launch_bounds__(TH1, 4)
void fb_pass1(const float* __restrict__ x, const float* __restrict__ W1, int n)
{
    extern __shared__ float smem[];
    float* W1s = smem;
    float* xcA = smem + 4096;
    float* xcB = smem + 8192;

    const int t     = threadIdx.x;
    const int row0  = blockIdx.x * RT1;
    const int nrows = min(RT1, n - row0);

    #pragma unroll
    for (int i = 0; i < 16; i++) W1s[t + i * TH1] = W1[t + i * TH1];

    // prologue: prefetch chunks 0 (A) and 1 (B)
    #pragma unroll
    for (int c = 0; c < 2; c++) {
        float* buf = c ? xcB : xcA;
        #pragma unroll
        for (int it = 0; it < 4; it++) {
            int idx = t + it * TH1;
            int rr = idx >> 2, q = idx & 3;
            if (rr < nrows)
                cpa16(buf + rr * CHUNK + 4 * (q ^ ((rr >> 1) & 3)),
                      x + (long long)(row0 + rr) * D + c * CHUNK + 4 * q);
        }
        cpa_commit();
    }

    const int r   = t;
    const int qs1 = (r >> 1) & 3;
    u64 acc[8];
    #pragma unroll
    for (int i = 0; i < 8; i++) acc[i] = 0ULL;

    for (int c = 0; c < NCH; c++) {
        if (c < NCH - 1) asm volatile("cp.async.wait_group 1;" ::: "memory");
        else             asm volatile("cp.async.wait_group 0;" ::: "memory");
        __syncthreads();

        const float* myrow = (c & 1 ? xcB : xcA) + r * CHUNK;
        const float* wbase = W1s + c * CHUNK * H;
        #pragma unroll
        for (int q = 0; q < 4; q++) {
            float4 xv = *reinterpret_cast<const float4*>(myrow + 4 * (q ^ qs1));
            #pragma unroll
            for (int i = 0; i < 4; i++) {
                float xs = (i == 0) ? xv.x : (i == 1) ? xv.y : (i == 2) ? xv.z : xv.w;
                u64 xx = pack2(xs, xs);
                const ulonglong2* wq =
                    reinterpret_cast<const ulonglong2*>(wbase + (4 * q + i) * H);
                ulonglong2 wa = wq[0], wb = wq[1];
                acc[0] = fma2(xx, wa.x, acc[0]);
                acc[1] = fma2(xx, wa.y, acc[1]);
                acc[2] = fma2(xx, wb.x, acc[2]);
                acc[3] = fma2(xx, wb.y, acc[3]);
                ulonglong2 wc = wq[2], wd = wq[3];
                acc[4] = fma2(xx, wc.x, acc[4]);
                acc[5] = fma2(xx, wc.y, acc[5]);
                acc[6] = fma2(xx, wd.x, acc[6]);
                acc[7] = fma2(xx, wd.y, acc[7]);
            }
        }
        __syncthreads();

        if (c + 2 < NCH) {
            float* buf = (c & 1) ? xcB : xcA;
            #pragma unroll
            for (int it = 0; it < 4; it++) {
                int idx = t + it * TH1;
                int rr = idx >> 2, q = idx & 3;
                if (rr < nrows)
                    cpa16(buf + rr * CHUNK + 4 * (q ^ ((rr >> 1) & 3)),
                          x + (long long)(row0 + rr) * D + (c + 2) * CHUNK + 4 * q);
            }
            cpa_commit();
        }
    }

    // ReLU + store h row to scratch (contiguous 64 B per thread)
    if (r < nrows) {
        float4* hd = reinterpret_cast<float4*>(h_scratch + (long long)(row0 + r) * H);
        #pragma unroll
        for (int q = 0; q < 4; q++) {
            float a0, a1, b0, b1;
            unpack2(acc[2 * q + 0], a0, a1);
            unpack2(acc[2 * q + 1], b0, b1);
            hd[q] = make_float4(fmaxf(a0, 0.f), fmaxf(a1, 0.f),
                                fmaxf(b0, 0.f), fmaxf(b1, 0.f));
        }
    }
}

// ============ Kernel 2: out = x * sigmoid(2 * h @ W2) =======================
__global__ __launch_bounds__(TH2, 6)
void fb_pass2(const float* __restrict__ x, const float* __restrict__ W2,
              float* __restrict__ out, int n)
{
    __shared__ __align__(16) float hs[RT2 * H];   // 8 KB

    const int t     = threadIdx.x;
    const int row0  = blockIdx.x * RT2;
    const int nrows = min(RT2, n - row0);

    // cooperative coalesced h-tile load
    const float4* hsrc = reinterpret_cast<const float4*>(h_scratch + (long long)row0 * H);
    for (int i = t; i < nrows * 4; i += TH2)
        reinterpret_cast<float4*>(hs)[i] = hsrc[i];
    __syncthreads();

    const int w = t >> 5, lane = t & 31;
    const int k = w * 32 + lane;            // 8 warps x 32 lanes = 256 k-cols

    u64 w2[8];                               // W2 column k, j-pairs
    #pragma unroll
    for (int j = 0; j < 8; j++)
        w2[j] = pack2(W2[(2 * j) * D + k], W2[(2 * j + 1) * D + k]);

    const float* xk = x   + (long long)row0 * D + k;
    float*       ok = out + (long long)row0 * D + k;

    float xp[4];                             // x prefetch ring (depth 4)
    #pragma unroll
    for (int i = 0; i < 4; i++)
        xp[i] = (i < nrows) ? xk[(long long)i * D] : 0.f;

    #pragma unroll 4
    for (int rr = 0; rr < nrows; rr++) {
        float xv = xp[rr & 3];
        if (rr + 4 < nrows) xp[rr & 3] = xk[(long long)(rr + 4) * D];

        const float* hr = hs + rr * H;       // uniform per warp -> broadcast
        u64 sa = 0ULL, sb = 0ULL;
        #pragma unroll
        for (int q = 0; q < 4; q++) {
            ulonglong2 hq = *reinterpret_cast<const ulonglong2*>(hr + 4 * q);
            sa = fma2(hq.x, w2[2 * q + 0], sa);
            sb = fma2(hq.y, w2[2 * q + 1], sb);
        }
        float a0, a1, b0, b1;
        unpack2(sa, a0, a1);
        unpack2(sb, b0, b1);
        float s = (a0 + b0) + (a1 + b1);

        ok[(long long)rr * D] = xv * sigmoid2(s);
    }
}

extern "C" void kernel_launch(void* const* d_in, const int* in_sizes, int n_in,
                              void* d_out, int out_size) {
    const float* x  = (const float*)d_in[0];
    const float* W1 = (const float*)d_in[1];
    const float* W2 = (const float*)d_in[2];
    float* out = (float*)d_out;
    int n = in_sizes[0] / D;

    int smem1 = (4096 + 2 * XCFL) * (int)sizeof(float);   // 48 KB
    cudaFuncSetAttribute(fb_pass1, cudaFuncAttributeMaxDynamicSharedMemorySize, smem1);

    int grid1 = (n + RT1 - 1) / RT1;
    int grid2 = (n + RT2 - 1) / RT2;
    fb_pass1<<<grid1, TH1, smem1>>>(x, W1, n);
    fb_pass2<<<grid2, TH2>>>(x, W2, out, n);
}